// round 9
// baseline (speedup 1.0000x reference)
#include <cuda_runtime.h>
#include <cuda_bf16.h>
#include <math.h>
#include <stdint.h>

#define B_ 8
#define T_ 512
#define E_ 1024
#define H_ 16
#define L_ 4
#define FF_ 4096
#define D_ 64
#define M_ 4096   // B*T

// ---------------- scratch (static device globals; no allocation) ----------------
__device__ float g_x[M_ * E_];
__device__ float g_qkv[M_ * 3 * E_];
__device__ float g_t1[M_ * FF_];
__device__ float g_t2[M_ * E_];
__device__ __nv_bfloat16 g_A[(size_t)M_ * 3 * FF_];   // activations hi/lo/hi (max M x 12288)
__device__ __nv_bfloat16 g_W[(size_t)FF_ * 3 * E_];   // weights hi/hi/lo (max 4096 x 3072)

// ================= helpers =================
__device__ __forceinline__ uint32_t smem_u32(const void* p) {
    uint32_t a;
    asm("{ .reg .u64 t; cvta.to.shared.u64 t, %1; cvt.u32.u64 %0, t; }" : "=r"(a) : "l"(p));
    return a;
}
__device__ __forceinline__ void cp16(uint32_t dst, const void* src) {
    asm volatile("cp.async.cg.shared.global [%0], [%1], 16;" :: "r"(dst), "l"(src) : "memory");
}
template <int N>
__device__ __forceinline__ void cpwait() {
    asm volatile("cp.async.wait_group %0;" :: "n"(N) : "memory");
}
__device__ __forceinline__ void cpcommit() {
    asm volatile("cp.async.commit_group;" ::: "memory");
}
__device__ __forceinline__ void ldsm_x4(uint32_t* r, uint32_t addr) {
    asm volatile("ldmatrix.sync.aligned.m8n8.x4.shared.b16 {%0,%1,%2,%3}, [%4];"
                 : "=r"(r[0]), "=r"(r[1]), "=r"(r[2]), "=r"(r[3]) : "r"(addr));
}
__device__ __forceinline__ void ldsm_x2(uint32_t* r, uint32_t addr) {
    asm volatile("ldmatrix.sync.aligned.m8n8.x2.shared.b16 {%0,%1}, [%2];"
                 : "=r"(r[0]), "=r"(r[1]) : "r"(addr));
}
__device__ __forceinline__ void mma16816(float* c, const uint32_t* a, const uint32_t* b) {
    asm volatile("mma.sync.aligned.m16n8k16.row.col.f32.bf16.bf16.f32 "
                 "{%0,%1,%2,%3}, {%4,%5,%6,%7}, {%8,%9}, {%0,%1,%2,%3};"
                 : "+f"(c[0]), "+f"(c[1]), "+f"(c[2]), "+f"(c[3])
                 : "r"(a[0]), "r"(a[1]), "r"(a[2]), "r"(a[3]), "r"(b[0]), "r"(b[1]));
}

// GEMM geometry: CTA 128x128, BK=32 bf16, 3 stages.
// smem rows padded to 80 bytes (32 bf16 = 64B data + 16B pad) -> conflict-free ldmatrix.
#define ROWB 80
#define HALF_STAGE (128 * ROWB)            // 10240 B (A or B tile)
#define STAGE_BYTES (2 * HALF_STAGE)       // 20480 B
#define GEMM_SMEM (3 * STAGE_BYTES)        // 61440 B

// ======================= HMMA GEMM: C = A'' @ W''^T + bias =======================
// A'' [Mdim x K3] bf16 row-major, W'' [Ndim x K3] bf16 row-major, C fp32 [Mdim x Ndim]
__device__ __forceinline__ void load_stage_mma(const __nv_bfloat16* A, const __nv_bfloat16* W,
                                               int bm, int bn, int K3, uint32_t sb, int s, int tid) {
    uint32_t ab = sb + (s % 3) * STAGE_BYTES;
    uint32_t bb = ab + HALF_STAGE;
    int k0 = s * 32;
#pragma unroll
    for (int i = 0; i < 2; i++) {
        int idx = tid + (i << 8);        // 0..511
        int row = idx >> 2, c = idx & 3; // row 0..127, 16B chunk 0..3
        cp16(ab + row * ROWB + c * 16, A + (size_t)(bm + row) * K3 + k0 + c * 8);
    }
#pragma unroll
    for (int i = 0; i < 2; i++) {
        int idx = tid + (i << 8);
        int row = idx >> 2, c = idx & 3;
        cp16(bb + row * ROWB + c * 16, W + (size_t)(bn + row) * K3 + k0 + c * 8);
    }
    cpcommit();
}

template <bool RELU>
__global__ void __launch_bounds__(256, 2)
gemm_mma_kernel(const __nv_bfloat16* __restrict__ A, const __nv_bfloat16* __restrict__ W,
                const float* __restrict__ bias, float* __restrict__ C, int Ndim, int K3) {
    extern __shared__ char smem[];
    uint32_t sb = smem_u32(smem);
    const int tid = threadIdx.x;
    const int wid = tid >> 5;
    const int lane = tid & 31;
    const int bm = blockIdx.y * 128;
    const int bn = blockIdx.x * 128;
    const int wm = (wid >> 2) * 64;   // warp m-origin (2 warps in m)
    const int wn = (wid & 3) * 32;    // warp n-origin (4 warps in n)

    // ldmatrix lane address components
    const int amat = lane >> 3;                       // 0..3
    const int arow_off = ((amat & 1) << 3) + (lane & 7);
    const int acol_off = (amat >> 1) << 4;            // 0 or 16 bytes
    const int brow_off = lane & 7;
    const int bcol_off = ((lane >> 3) & 1) << 4;

    float acc[4][4][4];
#pragma unroll
    for (int i = 0; i < 4; i++)
#pragma unroll
        for (int j = 0; j < 4; j++)
#pragma unroll
            for (int q = 0; q < 4; q++) acc[i][j][q] = 0.f;

    const int NK = K3 >> 5;   // BK=32
    load_stage_mma(A, W, bm, bn, K3, sb, 0, tid);
    load_stage_mma(A, W, bm, bn, K3, sb, 1, tid);

    for (int ks = 0; ks < NK; ks++) {
        if (ks == NK - 1) cpwait<0>(); else cpwait<1>();
        __syncthreads();
        if (ks + 2 < NK) load_stage_mma(A, W, bm, bn, K3, sb, ks + 2, tid);

        uint32_t ab = sb + (ks % 3) * STAGE_BYTES;
        uint32_t bb = ab + HALF_STAGE;
#pragma unroll
        for (int kk = 0; kk < 2; kk++) {        // two k16 steps per BK=32
            uint32_t afr[4][4], bfr[4][2];
#pragma unroll
            for (int mt = 0; mt < 4; mt++)
                ldsm_x4(afr[mt], ab + (wm + mt * 16 + arow_off) * ROWB + kk * 32 + acol_off);
#pragma unroll
            for (int nt = 0; nt < 4; nt++)
                ldsm_x2(bfr[nt], bb + (wn + nt * 8 + brow_off) * ROWB + kk * 32 + bcol_off);
#pragma unroll
            for (int mt = 0; mt < 4; mt++)
#pragma unroll
                for (int nt = 0; nt < 4; nt++)
                    mma16816(acc[mt][nt], afr[mt], bfr[nt]);
        }
    }

    // epilogue: c0,c1 -> (row g, col 2t), c2,c3 -> (row g+8, col 2t)
    const int g = lane >> 2;
    const int t = lane & 3;
#pragma unroll
    for (int mt = 0; mt < 4; mt++) {
#pragma unroll
        for (int nt = 0; nt < 4; nt++) {
            int row = bm + wm + mt * 16 + g;
            int col = bn + wn + nt * 8 + t * 2;
            float b0 = bias[col], b1 = bias[col + 1];
            float2 v0 = make_float2(acc[mt][nt][0] + b0, acc[mt][nt][1] + b1);
            float2 v1 = make_float2(acc[mt][nt][2] + b0, acc[mt][nt][3] + b1);
            if (RELU) {
                v0.x = fmaxf(v0.x, 0.f); v0.y = fmaxf(v0.y, 0.f);
                v1.x = fmaxf(v1.x, 0.f); v1.y = fmaxf(v1.y, 0.f);
            }
            *(float2*)&C[(size_t)row * Ndim + col] = v0;
            *(float2*)&C[(size_t)(row + 8) * Ndim + col] = v1;
        }
    }
}

// ================= fp32 -> bf16 hi/lo split with K-concat (x3) =================
// ISACT: out segs = [hi, lo, hi]   (activations)
// else:  out segs = [hi, hi, lo]   (weights)
template <bool ISACT>
__global__ void convert_hilo_kernel(const float* __restrict__ in, __nv_bfloat16* __restrict__ out,
                                    int K, int total) {
    int idx = blockIdx.x * blockDim.x + threadIdx.x;
    if (idx >= total) return;
    int r = idx / K;
    int k = idx - r * K;
    float v = in[idx];
    __nv_bfloat16 h = __float2bfloat16(v);
    float lof = v - __bfloat162float(h);
    __nv_bfloat16 lo = __float2bfloat16(lof);
    size_t base = (size_t)r * 3 * K;
    out[base + k] = h;
    out[base + K + k] = ISACT ? lo : h;
    out[base + 2 * K + k] = ISACT ? h : lo;
}

// ---------------- positional encoding ----------------
__global__ void pe_add_kernel(const float* __restrict__ src, float* __restrict__ x) {
    int idx = blockIdx.x * blockDim.x + threadIdx.x;
    int e = idx & (E_ - 1);
    int bt = idx >> 10;
    int b = bt >> 9;
    float pos = (float)b;
    int even = e & ~1;
    float freq = __expf(-(float)even * (9.210340371976184f / (float)E_));
    float pe = (e & 1) ? __cosf(pos * freq) : __sinf(pos * freq);
    x[idx] = src[idx] + pe;
}

// ---------------- fused attention (flash-style, gaussian reweight) ----------------
__global__ void __launch_bounds__(256, 2)
attention_kernel(const float* __restrict__ qkv, float* __restrict__ o) {
    __shared__ float Qs[64][68];
    __shared__ float Ks[32][68];
    __shared__ float Vs[32][68];
    __shared__ float Ps[64][33];

    const int qt = blockIdx.x * 64;
    const int h = blockIdx.y;
    const int b = blockIdx.z;
    const int tid = threadIdx.x;

    const float scl = 0.125f;
    const float inv2s2 = 1.f / 32768.f;

    for (int i = tid; i < 64 * 16; i += 256) {
        int r = i >> 4, c = (i & 15) * 4;
        float4 v = *(const float4*)&qkv[(size_t)(b * T_ + qt + r) * (3 * E_) + h * D_ + c];
        *(float4*)&Qs[r][c] = v;
    }

    const int qrow = tid >> 2;
    const int sub = tid & 3;
    const int qg = qt + qrow;
    const int dbase = sub * 16;

    __syncthreads();
    float4 qr[16];
#pragma unroll
    for (int c = 0; c < 16; c++) qr[c] = *(const float4*)&Qs[qrow][c * 4];

    float m = -1e30f, Z = 0.f, S = 0.f;
    float4 acc[4];
#pragma unroll
    for (int i = 0; i < 4; i++) acc[i] = make_float4(0.f, 0.f, 0.f, 0.f);

    for (int kt = 0; kt < T_; kt += 32) {
        __syncthreads();
        for (int i = tid; i < 32 * 16; i += 256) {
            int r = i >> 4, c = (i & 15) * 4;
            size_t base = (size_t)(b * T_ + kt + r) * (3 * E_) + h * D_ + c;
            *(float4*)&Ks[r][c] = *(const float4*)&qkv[base + E_];
            *(float4*)&Vs[r][c] = *(const float4*)&qkv[base + 2 * E_];
        }
        __syncthreads();

        float sv[8];
        float tmax = -1e30f;
#pragma unroll
        for (int jj = 0; jj < 8; jj++) {
            int j = sub * 8 + jj;
            const float4* kp = (const float4*)&Ks[j][0];
            float dot = 0.f;
#pragma unroll
            for (int c = 0; c < 16; c++) {
                float4 a = qr[c], k4 = kp[c];
                dot += a.x * k4.x + a.y * k4.y + a.z * k4.z + a.w * k4.w;
            }
            sv[jj] = dot * scl;
            tmax = fmaxf(tmax, sv[jj]);
        }
        tmax = fmaxf(tmax, __shfl_xor_sync(0xffffffffu, tmax, 1));
        tmax = fmaxf(tmax, __shfl_xor_sync(0xffffffffu, tmax, 2));
        float mnew = fmaxf(m, tmax);
        float corr = __expf(m - mnew);

        float zt = 0.f, st = 0.f;
#pragma unroll
        for (int jj = 0; jj < 8; jj++) {
            int j = sub * 8 + jj;
            float e = __expf(sv[jj] - mnew);
            float dd = (float)(qg - (kt + j));
            float gb = __expf(-dd * dd * inv2s2);
            float u = e * gb;
            zt += e; st += u;
            Ps[qrow][j] = u;
        }
        zt += __shfl_xor_sync(0xffffffffu, zt, 1);
        zt += __shfl_xor_sync(0xffffffffu, zt, 2);
        st += __shfl_xor_sync(0xffffffffu, st, 1);
        st += __shfl_xor_sync(0xffffffffu, st, 2);
        Z = Z * corr + zt;
        S = S * corr + st;
        m = mnew;
#pragma unroll
        for (int i = 0; i < 4; i++) {
            acc[i].x *= corr; acc[i].y *= corr; acc[i].z *= corr; acc[i].w *= corr;
        }
        __syncwarp();

#pragma unroll 4
        for (int j = 0; j < 32; j++) {
            float p = Ps[qrow][j];
            const float4* vp = (const float4*)&Vs[j][dbase];
#pragma unroll
            for (int i = 0; i < 4; i++) {
                float4 v = vp[i];
                acc[i].x = fmaf(p, v.x, acc[i].x);
                acc[i].y = fmaf(p, v.y, acc[i].y);
                acc[i].z = fmaf(p, v.z, acc[i].z);
                acc[i].w = fmaf(p, v.w, acc[i].w);
            }
        }
        __syncwarp();
    }

    float inv = 1.f / (S + 1e-5f * Z);
    float* op = &o[(size_t)(b * T_ + qg) * E_ + h * D_ + dbase];
#pragma unroll
    for (int i = 0; i < 4; i++) {
        float4 v = acc[i];
        v.x *= inv; v.y *= inv; v.z *= inv; v.w *= inv;
        *(float4*)(op + i * 4) = v;
    }
}

// ---------------- fused residual add + LayerNorm (in-place on x) ----------------
__global__ void add_ln_kernel(float* __restrict__ x, const float* __restrict__ r,
                              const float* __restrict__ g, const float* __restrict__ bb) {
    __shared__ float red[2][8];
    const int row = blockIdx.x;
    const int tid = threadIdx.x;
    float* xp = x + (size_t)row * E_;
    const float* rp = r + (size_t)row * E_;

    float4 xv = *(const float4*)&xp[tid * 4];
    float4 rv = *(const float4*)&rp[tid * 4];
    float4 v = make_float4(xv.x + rv.x, xv.y + rv.y, xv.z + rv.z, xv.w + rv.w);
    float s = v.x + v.y + v.z + v.w;
    float s2 = v.x * v.x + v.y * v.y + v.z * v.z + v.w * v.w;

#pragma unroll
    for (int o = 16; o > 0; o >>= 1) {
        s += __shfl_xor_sync(0xffffffffu, s, o);
        s2 += __shfl_xor_sync(0xffffffffu, s2, o);
    }
    int warp = tid >> 5, lane = tid & 31;
    if (lane == 0) { red[0][warp] = s; red[1][warp] = s2; }
    __syncthreads();
    if (warp == 0) {
        s = red[0][lane & 7]; s2 = red[1][lane & 7];
#pragma unroll
        for (int o = 4; o > 0; o >>= 1) {
            s += __shfl_xor_sync(0xffffffffu, s, o);
            s2 += __shfl_xor_sync(0xffffffffu, s2, o);
        }
        if (lane == 0) { red[0][0] = s; red[1][0] = s2; }
    }
    __syncthreads();
    float mu = red[0][0] * (1.f / E_);
    float var = red[1][0] * (1.f / E_) - mu * mu;
    float is = rsqrtf(var + 1e-5f);

    float4 gv = *(const float4*)&g[tid * 4];
    float4 bv = *(const float4*)&bb[tid * 4];
    float4 ov;
    ov.x = (v.x - mu) * is * gv.x + bv.x;
    ov.y = (v.y - mu) * is * gv.y + bv.y;
    ov.z = (v.z - mu) * is * gv.z + bv.z;
    ov.w = (v.w - mu) * is * gv.w + bv.w;
    *(float4*)&xp[tid * 4] = ov;
}

// ---------------- head ----------------
__global__ void head_kernel(const float* __restrict__ x, const float* __restrict__ hw,
                            const float* __restrict__ hb, float* __restrict__ out) {
    __shared__ float red[8];
    const int b = blockIdx.x;
    const int tid = threadIdx.x;
    const float* xp = x + ((size_t)(b * T_ + T_ - 1)) * E_;
    float4 xv = *(const float4*)&xp[tid * 4];
    float4 wv = *(const float4*)&hw[tid * 4];
    float s = xv.x * wv.x + xv.y * wv.y + xv.z * wv.z + xv.w * wv.w;
#pragma unroll
    for (int o = 16; o > 0; o >>= 1) s += __shfl_xor_sync(0xffffffffu, s, o);
    int warp = tid >> 5, lane = tid & 31;
    if (lane == 0) red[warp] = s;
    __syncthreads();
    if (tid == 0) {
        float t = 0.f;
#pragma unroll
        for (int w = 0; w < 8; w++) t += red[w];
        out[b] = t + hb[0];
    }
}

// ---------------- launch ----------------
static void conv_act(const float* in, __nv_bfloat16* out, int K, int rows) {
    int n = rows * K;
    convert_hilo_kernel<true><<<(n + 255) / 256, 256>>>(in, out, K, n);
}
static void conv_w(const float* in, __nv_bfloat16* out, int K, int rows) {
    int n = rows * K;
    convert_hilo_kernel<false><<<(n + 255) / 256, 256>>>(in, out, K, n);
}

extern "C" void kernel_launch(void* const* d_in, const int* in_sizes, int n_in,
                              void* d_out, int out_size) {
    const float* src       = (const float*)d_in[0];
    const float* in_proj_w = (const float*)d_in[1];
    const float* in_proj_b = (const float*)d_in[2];
    const float* out_w     = (const float*)d_in[3];
    const float* out_b     = (const float*)d_in[4];
    const float* ff1_w     = (const float*)d_in[5];
    const float* ff1_b     = (const float*)d_in[6];
    const float* ff2_w     = (const float*)d_in[7];
    const float* ff2_b     = (const float*)d_in[8];
    const float* ln1_g     = (const float*)d_in[9];
    const float* ln1_b     = (const float*)d_in[10];
    const float* ln2_g     = (const float*)d_in[11];
    const float* ln2_b     = (const float*)d_in[12];
    const float* head_w    = (const float*)d_in[13];
    const float* head_b    = (const float*)d_in[14];
    float* out = (float*)d_out;

    float *x, *qkv, *t1, *t2;
    __nv_bfloat16 *gA, *gW;
    cudaGetSymbolAddress((void**)&x, g_x);
    cudaGetSymbolAddress((void**)&qkv, g_qkv);
    cudaGetSymbolAddress((void**)&t1, g_t1);
    cudaGetSymbolAddress((void**)&t2, g_t2);
    cudaGetSymbolAddress((void**)&gA, g_A);
    cudaGetSymbolAddress((void**)&gW, g_W);

    cudaFuncSetAttribute(gemm_mma_kernel<false>, cudaFuncAttributeMaxDynamicSharedMemorySize, GEMM_SMEM);
    cudaFuncSetAttribute(gemm_mma_kernel<true>,  cudaFuncAttributeMaxDynamicSharedMemorySize, GEMM_SMEM);

    pe_add_kernel<<<(M_ * E_) / 256, 256>>>(src, x);

    for (int l = 0; l < L_; l++) {
        const float* ipw = in_proj_w + (size_t)l * 3 * E_ * E_;
        const float* ipb = in_proj_b + (size_t)l * 3 * E_;
        const float* ow  = out_w + (size_t)l * E_ * E_;
        const float* ob  = out_b + (size_t)l * E_;
        const float* f1w = ff1_w + (size_t)l * FF_ * E_;
        const float* f1b = ff1_b + (size_t)l * FF_;
        const float* f2w = ff2_w + (size_t)l * E_ * FF_;
        const float* f2b = ff2_b + (size_t)l * E_;

        // QKV projection: (M x 3E) = x @ ipw^T
        conv_act(x, gA, E_, M_);
        conv_w(ipw, gW, E_, 3 * E_);
        gemm_mma_kernel<false><<<dim3(3 * E_ / 128, M_ / 128), 256, GEMM_SMEM>>>(
            gA, gW, ipb, qkv, 3 * E_, 3 * E_);

        // attention -> t1 (M x E view)
        attention_kernel<<<dim3(T_ / 64, H_, B_), 256>>>(qkv, t1);

        // out projection -> t2
        conv_act(t1, gA, E_, M_);
        conv_w(ow, gW, E_, E_);
        gemm_mma_kernel<false><<<dim3(E_ / 128, M_ / 128), 256, GEMM_SMEM>>>(
            gA, gW, ob, t2, E_, 3 * E_);

        add_ln_kernel<<<M_, 256>>>(x, t2, ln1_g + (size_t)l * E_, ln1_b + (size_t)l * E_);

        // FF1 (+ReLU) -> t1 (M x FF)
        conv_act(x, gA, E_, M_);
        conv_w(f1w, gW, E_, FF_);
        gemm_mma_kernel<true><<<dim3(FF_ / 128, M_ / 128), 256, GEMM_SMEM>>>(
            gA, gW, f1b, t1, FF_, 3 * E_);

        // FF2 -> t2
        conv_act(t1, gA, FF_, M_);
        conv_w(f2w, gW, FF_, E_);
        gemm_mma_kernel<false><<<dim3(E_ / 128, M_ / 128), 256, GEMM_SMEM>>>(
            gA, gW, f2b, t2, E_, 3 * FF_);

        add_ln_kernel<<<M_, 256>>>(x, t2, ln2_g + (size_t)l * E_, ln2_b + (size_t)l * E_);
    }

    head_kernel<<<B_, 256>>>(x, head_w, head_b, out);
}

// round 10
// speedup vs baseline: 1.0307x; 1.0307x over previous
#include <cuda_runtime.h>
#include <cuda_bf16.h>
#include <math.h>
#include <stdint.h>

#define B_ 8
#define T_ 512
#define E_ 1024
#define H_ 16
#define L_ 4
#define FF_ 4096
#define D_ 64
#define M_ 4096   // B*T

// ---------------- scratch (static device globals; no allocation) ----------------
__device__ float g_x[M_ * E_];                          // activations fp32
__device__ float g_qkv[M_ * 3 * E_];                    // qkv fp32
__device__ float g_t2[M_ * E_];                         // residual branch fp32
__device__ __nv_bfloat16 g_A[(size_t)M_ * 3 * E_];      // hi/lo/hi activations (E-wide)
__device__ __nv_bfloat16 g_Af[(size_t)M_ * 3 * FF_];    // hi/lo/hi FF1 output (FF-wide)
__device__ __nv_bfloat16 g_W[(size_t)FF_ * 3 * E_];     // weights hi/hi/lo (max 12.6M elem)

// ================= helpers =================
__device__ __forceinline__ uint32_t smem_u32(const void* p) {
    uint32_t a;
    asm("{ .reg .u64 t; cvta.to.shared.u64 t, %1; cvt.u32.u64 %0, t; }" : "=r"(a) : "l"(p));
    return a;
}
__device__ __forceinline__ void cp16(uint32_t dst, const void* src) {
    asm volatile("cp.async.cg.shared.global [%0], [%1], 16;" :: "r"(dst), "l"(src) : "memory");
}
template <int N>
__device__ __forceinline__ void cpwait() {
    asm volatile("cp.async.wait_group %0;" :: "n"(N) : "memory");
}
__device__ __forceinline__ void cpcommit() {
    asm volatile("cp.async.commit_group;" ::: "memory");
}
__device__ __forceinline__ void ldsm_x4(uint32_t* r, uint32_t addr) {
    asm volatile("ldmatrix.sync.aligned.m8n8.x4.shared.b16 {%0,%1,%2,%3}, [%4];"
                 : "=r"(r[0]), "=r"(r[1]), "=r"(r[2]), "=r"(r[3]) : "r"(addr));
}
__device__ __forceinline__ void mma16816(float* c, const uint32_t* a, const uint32_t* b) {
    asm volatile("mma.sync.aligned.m16n8k16.row.col.f32.bf16.bf16.f32 "
                 "{%0,%1,%2,%3}, {%4,%5,%6,%7}, {%8,%9}, {%0,%1,%2,%3};"
                 : "+f"(c[0]), "+f"(c[1]), "+f"(c[2]), "+f"(c[3])
                 : "r"(a[0]), "r"(a[1]), "r"(a[2]), "r"(a[3]), "r"(b[0]), "r"(b[1]));
}

// hi/lo/hi write of a pair of consecutive values at (base, col), segment stride N
__device__ __forceinline__ void write_hl(__nv_bfloat16* base, int N, int col, float a, float b) {
    __nv_bfloat162 h, l;
    h.x = __float2bfloat16(a); h.y = __float2bfloat16(b);
    l.x = __float2bfloat16(a - __bfloat162float(h.x));
    l.y = __float2bfloat16(b - __bfloat162float(h.y));
    *(uint32_t*)(base + col)         = *(uint32_t*)&h;
    *(uint32_t*)(base + N + col)     = *(uint32_t*)&l;
    *(uint32_t*)(base + 2 * N + col) = *(uint32_t*)&h;
}

// GEMM geometry: CTA 128x128, BK=32 bf16, 4 stages.
// smem rows padded to 80 bytes (32 bf16 = 64B data + 16B pad) -> conflict-free ldmatrix.
#define ROWB 80
#define HALF_STAGE (128 * ROWB)            // 10240 B (A or B tile)
#define STAGE_BYTES (2 * HALF_STAGE)       // 20480 B
#define NSTAGE 4
#define GEMM_SMEM (NSTAGE * STAGE_BYTES)   // 81920 B

// ======================= HMMA GEMM: C = A'' @ W''^T + bias =======================
// A'' [Mdim x K3] bf16 row-major, W'' [Ndim x K3] bf16 row-major.
// WHL=false: C fp32 [Mdim x Ndim].  WHL=true: C bf16 hi/lo/hi [Mdim x 3*Ndim].
__device__ __forceinline__ void load_stage_mma(const __nv_bfloat16* A, const __nv_bfloat16* W,
                                               int bm, int bn, int K3, uint32_t sb, int s, int tid) {
    uint32_t ab = sb + (s % NSTAGE) * STAGE_BYTES;
    uint32_t bb = ab + HALF_STAGE;
    int k0 = s * 32;
#pragma unroll
    for (int i = 0; i < 2; i++) {
        int idx = tid + (i << 8);        // 0..511
        int row = idx >> 2, c = idx & 3; // row 0..127, 16B chunk 0..3
        cp16(ab + row * ROWB + c * 16, A + (size_t)(bm + row) * K3 + k0 + c * 8);
    }
#pragma unroll
    for (int i = 0; i < 2; i++) {
        int idx = tid + (i << 8);
        int row = idx >> 2, c = idx & 3;
        cp16(bb + row * ROWB + c * 16, W + (size_t)(bn + row) * K3 + k0 + c * 8);
    }
    cpcommit();
}

template <bool RELU, bool WHL>
__global__ void __launch_bounds__(256, 2)
gemm_mma_kernel(const __nv_bfloat16* __restrict__ A, const __nv_bfloat16* __restrict__ W,
                const float* __restrict__ bias, void* __restrict__ Cv, int Ndim, int K3) {
    extern __shared__ char smem[];
    uint32_t sb = smem_u32(smem);
    const int tid = threadIdx.x;
    const int wid = tid >> 5;
    const int lane = tid & 31;
    const int bm = blockIdx.y * 128;
    const int bn = blockIdx.x * 128;
    const int wm = (wid >> 2) * 64;   // warp m-origin (2 warps in m)
    const int wn = (wid & 3) * 32;    // warp n-origin (4 warps in n)

    // ldmatrix lane address components
    const int amat = lane >> 3;                       // 0..3
    const int arow_off = ((amat & 1) << 3) + (lane & 7);
    const int acol_off = (amat >> 1) << 4;            // 0 or 16 bytes
    // B paired x4: matrices {nt rows k0-7, nt rows k8-15, nt+8 rows k0-7, nt+8 rows k8-15}
    const int brow_off = (lane & 7) + ((lane >> 4) << 3);
    const int bcol_off = ((lane >> 3) & 1) << 4;

    float acc[4][4][4];
#pragma unroll
    for (int i = 0; i < 4; i++)
#pragma unroll
        for (int j = 0; j < 4; j++)
#pragma unroll
            for (int q = 0; q < 4; q++) acc[i][j][q] = 0.f;

    const int NK = K3 >> 5;   // BK=32
    load_stage_mma(A, W, bm, bn, K3, sb, 0, tid);
    load_stage_mma(A, W, bm, bn, K3, sb, 1, tid);
    load_stage_mma(A, W, bm, bn, K3, sb, 2, tid);

    for (int ks = 0; ks < NK; ks++) {
        if (ks < NK - 2)       cpwait<2>();
        else if (ks == NK - 2) cpwait<1>();
        else                   cpwait<0>();
        __syncthreads();
        if (ks + 3 < NK) load_stage_mma(A, W, bm, bn, K3, sb, ks + 3, tid);

        uint32_t ab = sb + (ks % NSTAGE) * STAGE_BYTES;
        uint32_t bb = ab + HALF_STAGE;
#pragma unroll
        for (int kk = 0; kk < 2; kk++) {        // two k16 steps per BK=32
            uint32_t afr[4][4], bfr[4][2];
#pragma unroll
            for (int mt = 0; mt < 4; mt++)
                ldsm_x4(afr[mt], ab + (wm + mt * 16 + arow_off) * ROWB + kk * 32 + acol_off);
#pragma unroll
            for (int ntp = 0; ntp < 2; ntp++) {
                uint32_t bq[4];
                ldsm_x4(bq, bb + (wn + ntp * 16 + brow_off) * ROWB + kk * 32 + bcol_off);
                bfr[2 * ntp][0] = bq[0]; bfr[2 * ntp][1] = bq[1];
                bfr[2 * ntp + 1][0] = bq[2]; bfr[2 * ntp + 1][1] = bq[3];
            }
#pragma unroll
            for (int mt = 0; mt < 4; mt++)
#pragma unroll
                for (int nt = 0; nt < 4; nt++)
                    mma16816(acc[mt][nt], afr[mt], bfr[nt]);
        }
    }

    // epilogue: c0,c1 -> (row g, col 2t), c2,c3 -> (row g+8, col 2t)
    const int g = lane >> 2;
    const int t = lane & 3;
#pragma unroll
    for (int mt = 0; mt < 4; mt++) {
#pragma unroll
        for (int nt = 0; nt < 4; nt++) {
            int row = bm + wm + mt * 16 + g;
            int col = bn + wn + nt * 8 + t * 2;
            float b0 = bias[col], b1 = bias[col + 1];
            float p0 = acc[mt][nt][0] + b0, p1 = acc[mt][nt][1] + b1;
            float p2 = acc[mt][nt][2] + b0, p3 = acc[mt][nt][3] + b1;
            if (RELU) {
                p0 = fmaxf(p0, 0.f); p1 = fmaxf(p1, 0.f);
                p2 = fmaxf(p2, 0.f); p3 = fmaxf(p3, 0.f);
            }
            if (WHL) {
                __nv_bfloat16* Cb = (__nv_bfloat16*)Cv;
                size_t rs = 3 * (size_t)Ndim;
                write_hl(Cb + (size_t)row * rs, Ndim, col, p0, p1);
                write_hl(Cb + (size_t)(row + 8) * rs, Ndim, col, p2, p3);
            } else {
                float* Cf = (float*)Cv;
                *(float2*)&Cf[(size_t)row * Ndim + col] = make_float2(p0, p1);
                *(float2*)&Cf[(size_t)(row + 8) * Ndim + col] = make_float2(p2, p3);
            }
        }
    }
}

// ================= weight fp32 -> bf16 hi/hi/lo K-concat =================
__global__ void conv_w_kernel(const float* __restrict__ in, __nv_bfloat16* __restrict__ out,
                              int K, int total) {
    int idx = blockIdx.x * blockDim.x + threadIdx.x;
    if (idx >= total) return;
    int r = idx / K;
    int k = idx - r * K;
    float v = in[idx];
    __nv_bfloat16 h = __float2bfloat16(v);
    __nv_bfloat16 lo = __float2bfloat16(v - __bfloat162float(h));
    size_t base = (size_t)r * 3 * K;
    out[base + k] = h;
    out[base + K + k] = h;
    out[base + 2 * K + k] = lo;
}

// ---------------- positional encoding: x = src + pe, also write hi/lo/hi ----------
__global__ void pe_add_kernel(const float* __restrict__ src, float* __restrict__ x,
                              __nv_bfloat16* __restrict__ ahl) {
    int i2 = blockIdx.x * blockDim.x + threadIdx.x;   // over (M*E)/2
    int idx = i2 * 2;
    int col = idx & (E_ - 1);                          // even
    int row = idx >> 10;
    int b = row >> 9;
    float pos = (float)b;
    float freq = __expf(-(float)col * (9.210340371976184f / (float)E_)); // even=col
    float2 sv = *(const float2*)&src[idx];
    float v0 = sv.x + __sinf(pos * freq);
    float v1 = sv.y + __cosf(pos * freq);
    *(float2*)&x[idx] = make_float2(v0, v1);
    write_hl(ahl + (size_t)row * 3 * E_, E_, col, v0, v1);
}

// ---------------- fused attention (flash-style, gaussian reweight) ----------------
// writes output directly as hi/lo/hi bf16 into ohl [M x 3E]
__global__ void __launch_bounds__(256, 2)
attention_kernel(const float* __restrict__ qkv, __nv_bfloat16* __restrict__ ohl) {
    __shared__ float Qs[64][68];
    __shared__ float Ks[32][68];
    __shared__ float Vs[32][68];
    __shared__ float Ps[64][33];

    const int qt = blockIdx.x * 64;
    const int h = blockIdx.y;
    const int b = blockIdx.z;
    const int tid = threadIdx.x;

    const float scl = 0.125f;
    const float inv2s2 = 1.f / 32768.f;

    for (int i = tid; i < 64 * 16; i += 256) {
        int r = i >> 4, c = (i & 15) * 4;
        float4 v = *(const float4*)&qkv[(size_t)(b * T_ + qt + r) * (3 * E_) + h * D_ + c];
        *(float4*)&Qs[r][c] = v;
    }

    const int qrow = tid >> 2;
    const int sub = tid & 3;
    const int qg = qt + qrow;
    const int dbase = sub * 16;

    __syncthreads();
    float4 qr[16];
#pragma unroll
    for (int c = 0; c < 16; c++) qr[c] = *(const float4*)&Qs[qrow][c * 4];

    float m = -1e30f, Z = 0.f, S = 0.f;
    float4 acc[4];
#pragma unroll
    for (int i = 0; i < 4; i++) acc[i] = make_float4(0.f, 0.f, 0.f, 0.f);

    for (int kt = 0; kt < T_; kt += 32) {
        __syncthreads();
        for (int i = tid; i < 32 * 16; i += 256) {
            int r = i >> 4, c = (i & 15) * 4;
            size_t base = (size_t)(b * T_ + kt + r) * (3 * E_) + h * D_ + c;
            *(float4*)&Ks[r][c] = *(const float4*)&qkv[base + E_];
            *(float4*)&Vs[r][c] = *(const float4*)&qkv[base + 2 * E_];
        }
        __syncthreads();

        float sv[8];
        float tmax = -1e30f;
#pragma unroll
        for (int jj = 0; jj < 8; jj++) {
            int j = sub * 8 + jj;
            const float4* kp = (const float4*)&Ks[j][0];
            float dot = 0.f;
#pragma unroll
            for (int c = 0; c < 16; c++) {
                float4 a = qr[c], k4 = kp[c];
                dot += a.x * k4.x + a.y * k4.y + a.z * k4.z + a.w * k4.w;
            }
            sv[jj] = dot * scl;
            tmax = fmaxf(tmax, sv[jj]);
        }
        tmax = fmaxf(tmax, __shfl_xor_sync(0xffffffffu, tmax, 1));
        tmax = fmaxf(tmax, __shfl_xor_sync(0xffffffffu, tmax, 2));
        float mnew = fmaxf(m, tmax);
        float corr = __expf(m - mnew);

        float zt = 0.f, st = 0.f;
#pragma unroll
        for (int jj = 0; jj < 8; jj++) {
            int j = sub * 8 + jj;
            float e = __expf(sv[jj] - mnew);
            float dd = (float)(qg - (kt + j));
            float gb = __expf(-dd * dd * inv2s2);
            float u = e * gb;
            zt += e; st += u;
            Ps[qrow][j] = u;
        }
        zt += __shfl_xor_sync(0xffffffffu, zt, 1);
        zt += __shfl_xor_sync(0xffffffffu, zt, 2);
        st += __shfl_xor_sync(0xffffffffu, st, 1);
        st += __shfl_xor_sync(0xffffffffu, st, 2);
        Z = Z * corr + zt;
        S = S * corr + st;
        m = mnew;
#pragma unroll
        for (int i = 0; i < 4; i++) {
            acc[i].x *= corr; acc[i].y *= corr; acc[i].z *= corr; acc[i].w *= corr;
        }
        __syncwarp();

#pragma unroll 4
        for (int j = 0; j < 32; j++) {
            float p = Ps[qrow][j];
            const float4* vp = (const float4*)&Vs[j][dbase];
#pragma unroll
            for (int i = 0; i < 4; i++) {
                float4 v = vp[i];
                acc[i].x = fmaf(p, v.x, acc[i].x);
                acc[i].y = fmaf(p, v.y, acc[i].y);
                acc[i].z = fmaf(p, v.z, acc[i].z);
                acc[i].w = fmaf(p, v.w, acc[i].w);
            }
        }
        __syncwarp();
    }

    float inv = 1.f / (S + 1e-5f * Z);
    __nv_bfloat16* op = ohl + (size_t)(b * T_ + qg) * (3 * E_);
    int colb = h * D_ + dbase;
#pragma unroll
    for (int i = 0; i < 4; i++) {
        float4 v = acc[i];
        v.x *= inv; v.y *= inv; v.z *= inv; v.w *= inv;
        write_hl(op, E_, colb + i * 4, v.x, v.y);
        write_hl(op, E_, colb + i * 4 + 2, v.z, v.w);
    }
}

// ------------- fused residual add + LayerNorm (in-place x) + hi/lo write ---------
__global__ void add_ln_kernel(float* __restrict__ x, const float* __restrict__ r,
                              const float* __restrict__ g, const float* __restrict__ bb,
                              __nv_bfloat16* __restrict__ ahl) {
    __shared__ float red[2][8];
    const int row = blockIdx.x;
    const int tid = threadIdx.x;
    float* xp = x + (size_t)row * E_;
    const float* rp = r + (size_t)row * E_;

    float4 xv = *(const float4*)&xp[tid * 4];
    float4 rv = *(const float4*)&rp[tid * 4];
    float4 v = make_float4(xv.x + rv.x, xv.y + rv.y, xv.z + rv.z, xv.w + rv.w);
    float s = v.x + v.y + v.z + v.w;
    float s2 = v.x * v.x + v.y * v.y + v.z * v.z + v.w * v.w;

#pragma unroll
    for (int o = 16; o > 0; o >>= 1) {
        s += __shfl_xor_sync(0xffffffffu, s, o);
        s2 += __shfl_xor_sync(0xffffffffu, s2, o);
    }
    int warp = tid >> 5, lane = tid & 31;
    if (lane == 0) { red[0][warp] = s; red[1][warp] = s2; }
    __syncthreads();
    if (warp == 0) {
        s = red[0][lane & 7]; s2 = red[1][lane & 7];
#pragma unroll
        for (int o = 4; o > 0; o >>= 1) {
            s += __shfl_xor_sync(0xffffffffu, s, o);
            s2 += __shfl_xor_sync(0xffffffffu, s2, o);
        }
        if (lane == 0) { red[0][0] = s; red[1][0] = s2; }
    }
    __syncthreads();
    float mu = red[0][0] * (1.f / E_);
    float var = red[1][0] * (1.f / E_) - mu * mu;
    float is = rsqrtf(var + 1e-5f);

    float4 gv = *(const float4*)&g[tid * 4];
    float4 bv = *(const float4*)&bb[tid * 4];
    float4 ov;
    ov.x = (v.x - mu) * is * gv.x + bv.x;
    ov.y = (v.y - mu) * is * gv.y + bv.y;
    ov.z = (v.z - mu) * is * gv.z + bv.z;
    ov.w = (v.w - mu) * is * gv.w + bv.w;
    *(float4*)&xp[tid * 4] = ov;

    __nv_bfloat16* ap = ahl + (size_t)row * 3 * E_;
    write_hl(ap, E_, tid * 4, ov.x, ov.y);
    write_hl(ap, E_, tid * 4 + 2, ov.z, ov.w);
}

// ---------------- head ----------------
__global__ void head_kernel(const float* __restrict__ x, const float* __restrict__ hw,
                            const float* __restrict__ hb, float* __restrict__ out) {
    __shared__ float red[8];
    const int b = blockIdx.x;
    const int tid = threadIdx.x;
    const float* xp = x + ((size_t)(b * T_ + T_ - 1)) * E_;
    float4 xv = *(const float4*)&xp[tid * 4];
    float4 wv = *(const float4*)&hw[tid * 4];
    float s = xv.x * wv.x + xv.y * wv.y + xv.z * wv.z + xv.w * wv.w;
#pragma unroll
    for (int o = 16; o > 0; o >>= 1) s += __shfl_xor_sync(0xffffffffu, s, o);
    int warp = tid >> 5, lane = tid & 31;
    if (lane == 0) red[warp] = s;
    __syncthreads();
    if (tid == 0) {
        float t = 0.f;
#pragma unroll
        for (int w = 0; w < 8; w++) t += red[w];
        out[b] = t + hb[0];
    }
}

// ---------------- launch ----------------
static void conv_w(const float* in, __nv_bfloat16* out, int K, int rows) {
    int n = rows * K;
    conv_w_kernel<<<(n + 255) / 256, 256>>>(in, out, K, n);
}

extern "C" void kernel_launch(void* const* d_in, const int* in_sizes, int n_in,
                              void* d_out, int out_size) {
    const float* src       = (const float*)d_in[0];
    const float* in_proj_w = (const float*)d_in[1];
    const float* in_proj_b = (const float*)d_in[2];
    const float* out_w     = (const float*)d_in[3];
    const float* out_b     = (const float*)d_in[4];
    const float* ff1_w     = (const float*)d_in[5];
    const float* ff1_b     = (const float*)d_in[6];
    const float* ff2_w     = (const float*)d_in[7];
    const float* ff2_b     = (const float*)d_in[8];
    const float* ln1_g     = (const float*)d_in[9];
    const float* ln1_b     = (const float*)d_in[10];
    const float* ln2_g     = (const float*)d_in[11];
    const float* ln2_b     = (const float*)d_in[12];
    const float* head_w    = (const float*)d_in[13];
    const float* head_b    = (const float*)d_in[14];
    float* out = (float*)d_out;

    float *x, *qkv, *t2;
    __nv_bfloat16 *gA, *gAf, *gW;
    cudaGetSymbolAddress((void**)&x, g_x);
    cudaGetSymbolAddress((void**)&qkv, g_qkv);
    cudaGetSymbolAddress((void**)&t2, g_t2);
    cudaGetSymbolAddress((void**)&gA, g_A);
    cudaGetSymbolAddress((void**)&gAf, g_Af);
    cudaGetSymbolAddress((void**)&gW, g_W);

    cudaFuncSetAttribute(gemm_mma_kernel<false, false>,
                         cudaFuncAttributeMaxDynamicSharedMemorySize, GEMM_SMEM);
    cudaFuncSetAttribute(gemm_mma_kernel<true, true>,
                         cudaFuncAttributeMaxDynamicSharedMemorySize, GEMM_SMEM);

    pe_add_kernel<<<(M_ * E_ / 2) / 256, 256>>>(src, x, gA);

    for (int l = 0; l < L_; l++) {
        const float* ipw = in_proj_w + (size_t)l * 3 * E_ * E_;
        const float* ipb = in_proj_b + (size_t)l * 3 * E_;
        const float* ow  = out_w + (size_t)l * E_ * E_;
        const float* ob  = out_b + (size_t)l * E_;
        const float* f1w = ff1_w + (size_t)l * FF_ * E_;
        const float* f1b = ff1_b + (size_t)l * FF_;
        const float* f2w = ff2_w + (size_t)l * E_ * FF_;
        const float* f2b = ff2_b + (size_t)l * E_;

        // QKV projection: qkv(fp32) = x_hl @ ipw_hl^T
        conv_w(ipw, gW, E_, 3 * E_);
        gemm_mma_kernel<false, false><<<dim3(3 * E_ / 128, M_ / 128), 256, GEMM_SMEM>>>(
            gA, gW, ipb, qkv, 3 * E_, 3 * E_);

        // attention -> g_A (hi/lo/hi)
        attention_kernel<<<dim3(T_ / 64, H_, B_), 256>>>(qkv, gA);

        // out projection -> t2 fp32
        conv_w(ow, gW, E_, E_);
        gemm_mma_kernel<false, false><<<dim3(E_ / 128, M_ / 128), 256, GEMM_SMEM>>>(
            gA, gW, ob, t2, E_, 3 * E_);

        // x = LN(x + t2), also writes x_hl -> g_A
        add_ln_kernel<<<M_, 256>>>(x, t2, ln1_g + (size_t)l * E_, ln1_b + (size_t)l * E_, gA);

        // FF1 (+ReLU) -> g_Af (hi/lo/hi, FF-wide)
        conv_w(f1w, gW, E_, FF_);
        gemm_mma_kernel<true, true><<<dim3(FF_ / 128, M_ / 128), 256, GEMM_SMEM>>>(
            gA, gW, f1b, gAf, FF_, 3 * E_);

        // FF2 -> t2 fp32
        conv_w(f2w, gW, FF_, E_);
        gemm_mma_kernel<false, false><<<dim3(E_ / 128, M_ / 128), 256, GEMM_SMEM>>>(
            gAf, gW, f2b, t2, E_, 3 * FF_);

        // x = LN(x + t2), also writes x_hl -> g_A
        add_ln_kernel<<<M_, 256>>>(x, t2, ln2_g + (size_t)l * E_, ln2_b + (size_t)l * E_, gA);
    }

    head_kernel<<<B_, 256>>>(x, head_w, head_b, out);
}